// round 8
// baseline (speedup 1.0000x reference)
#include <cuda_runtime.h>

// ---------------------------------------------------------------------------
// 2-layer KAN (1 -> 8 -> 1) == scalar function out = f(x).
// FUSED single kernel:
//   - blocks 0..NPROD-1 first build a piecewise-cubic LUT of f on [-8,8)
//     (N=512 intervals, h=1/32 exact) into g_coef, publish via g_done;
//   - ALL 512 blocks (producers included) then: x already loading since kernel
//     start, spin-wait for g_done==NPROD (thread 0 + nanosleep backoff),
//     stage the 8KB LUT to shared via __ldcg, evaluate each element with one
//     random LDS.128 + Horner. Exact fallback for |x|>=8 (never hit, N(0,1)).
//   - replay-safe: last finishing block resets g_done/g_fin to 0.
// Producers never wait on consumers -> no deadlock regardless of residency.
// ---------------------------------------------------------------------------

#define LUT_N    512
#define LUT_INVH 32.0f          // 1/h, exact
#define LUT_H    (1.0f / 32.0f) // h,   exact
#define LUT_OFS  256.0f         // 8*32, exact
#define NPROD    18             // ceil(512 / 29) producer blocks

__device__ __align__(16) float4 g_coef[LUT_N];
__device__ int g_done = 0;      // producers finished counter
__device__ int g_fin  = 0;      // blocks finished counter (for reset)

__device__ __forceinline__ float silu_f(float x) {
    return x * __fdividef(1.0f, 1.0f + __expf(-x));
}

__device__ __forceinline__ void spline_basis(float s, float jf, float* b) {
    const float c6 = 1.0f / 6.0f;
    float t = s - jf;
    float u = 1.0f - t;
    float t2 = t * t, t3 = t2 * t;
    b[0] = u * u * u * c6;
    b[1] = (3.0f * t3 - 6.0f * t2 + 4.0f) * c6;
    b[2] = (-3.0f * t3 + 3.0f * t2 + 3.0f * t + 1.0f) * c6;
    b[3] = t3 * c6;
}

// Per-unit contribution to f(x): layer1 unit u -> h, then layer2 unit u on h.
__device__ __forceinline__ float kan_unit(float x, int u,
    const float* __restrict__ bw1, const float* __restrict__ sw1,
    const float* __restrict__ sc1, const float* __restrict__ bw2,
    const float* __restrict__ sw2, const float* __restrict__ sc2)
{
    float h = silu_f(x) * __ldg(bw1 + u);
    float s = (x + 2.2f) * 2.5f;
    float jf = floorf(s);
    int j = (int)jf;
    if (j >= 0 && j <= 10) {
        float b[4];
        spline_basis(s, jf, b);
        float sc = __ldg(sc1 + u);
        #pragma unroll
        for (int m = 0; m < 4; m++) {
            int ri = j - 3 + m;
            if (ri >= 0 && ri < 8) h += b[m] * __ldg(sw1 + u * 8 + ri) * sc;
        }
    }
    float c = silu_f(h) * __ldg(bw2 + u);
    float s2 = (h + 2.2f) * 2.5f;
    float jf2 = floorf(s2);
    int j2 = (int)jf2;
    if (j2 >= 0 && j2 <= 10) {
        float b[4];
        spline_basis(s2, jf2, b);
        float sc = __ldg(sc2 + u);
        #pragma unroll
        for (int m = 0; m < 4; m++) {
            int ri = j2 - 3 + m;
            if (ri >= 0 && ri < 8) c += b[m] * __ldg(sw2 + u * 8 + ri) * sc;
        }
    }
    return c;
}

// Full exact eval (fallback for out-of-table x).
__device__ float kan_exact(float x,
    const float* __restrict__ bw1, const float* __restrict__ sw1,
    const float* __restrict__ sc1, const float* __restrict__ bw2,
    const float* __restrict__ sw2, const float* __restrict__ sc2)
{
    float acc = 0.0f;
    #pragma unroll
    for (int u = 0; u < 8; u++)
        acc += kan_unit(x, u, bw1, sw1, sc1, bw2, sw2, sc2);
    return acc;
}

__global__ __launch_bounds__(256)
void kan_fused_kernel(const float4* __restrict__ xv, float4* __restrict__ outv,
                      const float* __restrict__ bw1, const float* __restrict__ sw1,
                      const float* __restrict__ sc1, const float* __restrict__ bw2,
                      const float* __restrict__ sw2, const float* __restrict__ sc2,
                      int n4)
{
    __shared__ __align__(16) float4 s_lut[LUT_N];
    __shared__ float s_y[32];

    int tid = threadIdx.x;
    int bid = blockIdx.x;
    int idx = bid * 256 + tid;

    // 1) Issue the x load immediately (hides DRAM latency under build/spin).
    bool valid = idx < n4;
    float4 xin = valid ? xv[idx] : make_float4(0.f, 0.f, 0.f, 0.f);

    // 2) Producer blocks build their 29-interval LUT slice.
    if (bid < NPROD) {
        int unit = tid & 7;
        int nl   = tid >> 3;                       // 0..31 local node
        int m    = bid * 29 - 1 + nl;
        float xn = fmaf((float)m, LUT_H, -8.0f);   // exact grid node

        float c = kan_unit(xn, unit, bw1, sw1, sc1, bw2, sw2, sc2);
        c += __shfl_xor_sync(0xffffffffu, c, 1);
        c += __shfl_xor_sync(0xffffffffu, c, 2);
        c += __shfl_xor_sync(0xffffffffu, c, 4);
        if (unit == 0) s_y[nl] = c;
        __syncthreads();

        if (tid < 29) {
            int k = bid * 29 + tid;
            if (k < LUT_N) {
                float y0 = s_y[tid], y1 = s_y[tid + 1];
                float y2 = s_y[tid + 2], y3 = s_y[tid + 3];
                // Lagrange cubic through (-1,y0),(0,y1),(1,y2),(2,y3):
                float c0 = y1;
                float c1 = -y0 * (1.0f/3.0f) - 0.5f * y1 + y2 - y3 * (1.0f/6.0f);
                float c2 =  0.5f * y0 - y1 + 0.5f * y2;
                float c3 = (y3 - y0) * (1.0f/6.0f) + 0.5f * (y1 - y2);
                g_coef[k] = make_float4(c0, c1, c2, c3);
            }
        }
        __syncthreads();
        __threadfence();                 // make LUT slice visible (L2)
        if (tid == 0) atomicAdd(&g_done, 1);
    }

    // 3) Wait until the whole LUT is published (thread 0 polls, backoff).
    if (tid == 0) {
        while (atomicAdd(&g_done, 0) < NPROD) __nanosleep(64);
    }
    __syncthreads();

    // 4) Stage LUT to shared. __ldcg reads L2 directly (coherence point),
    //    so producer writes are guaranteed visible after the flag.
    s_lut[tid]       = __ldcg(&g_coef[tid]);
    s_lut[tid + 256] = __ldcg(&g_coef[tid + 256]);
    __syncthreads();

    // 5) Evaluate: one random LDS.128 + Horner per element.
    float xs[4] = {xin.x, xin.y, xin.z, xin.w};
    float r[4];
    bool oor_any = false;
    unsigned oor_mask = 0;

    #pragma unroll
    for (int e = 0; e < 4; e++) {
        float x = xs[e];
        float s = fmaf(x, LUT_INVH, LUT_OFS);
        float kf = floorf(s);
        int k = (int)kf;
        bool oo = (k < 0) | (k >= LUT_N);
        oor_any |= oo;
        if (oo) oor_mask |= 1u << e;
        k = max(0, min(LUT_N - 1, k));
        float u = fmaf(x, LUT_INVH, LUT_OFS - (float)k);
        float4 cf = s_lut[k];
        r[e] = fmaf(fmaf(fmaf(cf.w, u, cf.z), u, cf.y), u, cf.x);
    }

    if (oor_any) {  // essentially never taken for N(0,1) inputs
        #pragma unroll
        for (int e = 0; e < 4; e++)
            if (oor_mask & (1u << e))
                r[e] = kan_exact(xs[e], bw1, sw1, sc1, bw2, sw2, sc2);
    }

    if (valid) outv[idx] = make_float4(r[0], r[1], r[2], r[3]);

    // 6) Replay-safe reset: last block to finish zeroes the flags.
    __syncthreads();
    if (tid == 0) {
        int old = atomicAdd(&g_fin, 1);
        if (old == (int)gridDim.x - 1) {
            g_done = 0;
            g_fin  = 0;
            __threadfence();
        }
    }
}

extern "C" void kernel_launch(void* const* d_in, const int* in_sizes, int n_in,
                              void* d_out, int out_size) {
    const float* x   = (const float*)d_in[0];
    const float* bw1 = (const float*)d_in[1];
    const float* sw1 = (const float*)d_in[2];
    const float* sc1 = (const float*)d_in[3];
    const float* bw2 = (const float*)d_in[4];
    const float* sw2 = (const float*)d_in[5];
    const float* sc2 = (const float*)d_in[6];

    int n  = in_sizes[0];   // 524288
    int n4 = n / 4;         // 131072

    int blocks = (n4 + 255) / 256;   // 512
    kan_fused_kernel<<<blocks, 256>>>((const float4*)x, (float4*)d_out,
                                      bw1, sw1, sc1, bw2, sw2, sc2, n4);
}

// round 9
// speedup vs baseline: 1.1875x; 1.1875x over previous
#include <cuda_runtime.h>

// ---------------------------------------------------------------------------
// 2-layer KAN (1 -> 8 -> 1) == scalar function out = f(x).
// Two kernels chained with PDL (programmatic dependent launch):
//   (1) build_lut_kernel: piecewise-cubic LUT of f on [-8,8), N=512 intervals
//       (h=1/32 exact), one thread per (node, unit); fires the programmatic
//       launch trigger right after publishing the LUT.
//   (2) kan_lut_kernel (launched with ProgrammaticStreamSerialization):
//       starts during (1)'s tail, issues its x LDG burst immediately, then
//       cudaGridDependencySynchronize() before staging the 8KB LUT to shared;
//       eval = one random LDS.128 + Horner. Exact fallback for |x|>=8.
// ---------------------------------------------------------------------------

#define LUT_N    512
#define LUT_INVH 32.0f          // 1/h, exact
#define LUT_H    (1.0f / 32.0f) // h,   exact
#define LUT_OFS  256.0f         // 8*32, exact

__device__ __align__(16) float4 g_coef[LUT_N];

__device__ __forceinline__ float silu_f(float x) {
    return x * __fdividef(1.0f, 1.0f + __expf(-x));
}

__device__ __forceinline__ void spline_basis(float s, float jf, float* b) {
    const float c6 = 1.0f / 6.0f;
    float t = s - jf;
    float u = 1.0f - t;
    float t2 = t * t, t3 = t2 * t;
    b[0] = u * u * u * c6;
    b[1] = (3.0f * t3 - 6.0f * t2 + 4.0f) * c6;
    b[2] = (-3.0f * t3 + 3.0f * t2 + 3.0f * t + 1.0f) * c6;
    b[3] = t3 * c6;
}

// Per-unit contribution to f(x): layer1 unit u -> h, then layer2 unit u on h.
__device__ __forceinline__ float kan_unit(float x, int u,
    const float* __restrict__ bw1, const float* __restrict__ sw1,
    const float* __restrict__ sc1, const float* __restrict__ bw2,
    const float* __restrict__ sw2, const float* __restrict__ sc2)
{
    float h = silu_f(x) * __ldg(bw1 + u);
    float s = (x + 2.2f) * 2.5f;
    float jf = floorf(s);
    int j = (int)jf;
    if (j >= 0 && j <= 10) {
        float b[4];
        spline_basis(s, jf, b);
        float sc = __ldg(sc1 + u);
        #pragma unroll
        for (int m = 0; m < 4; m++) {
            int ri = j - 3 + m;
            if (ri >= 0 && ri < 8) h += b[m] * __ldg(sw1 + u * 8 + ri) * sc;
        }
    }
    float c = silu_f(h) * __ldg(bw2 + u);
    float s2 = (h + 2.2f) * 2.5f;
    float jf2 = floorf(s2);
    int j2 = (int)jf2;
    if (j2 >= 0 && j2 <= 10) {
        float b[4];
        spline_basis(s2, jf2, b);
        float sc = __ldg(sc2 + u);
        #pragma unroll
        for (int m = 0; m < 4; m++) {
            int ri = j2 - 3 + m;
            if (ri >= 0 && ri < 8) c += b[m] * __ldg(sw2 + u * 8 + ri) * sc;
        }
    }
    return c;
}

// Full exact eval (fallback for out-of-table x in main kernel).
__device__ float kan_exact(float x,
    const float* __restrict__ bw1, const float* __restrict__ sw1,
    const float* __restrict__ sc1, const float* __restrict__ bw2,
    const float* __restrict__ sw2, const float* __restrict__ sc2)
{
    float acc = 0.0f;
    #pragma unroll
    for (int u = 0; u < 8; u++)
        acc += kan_unit(x, u, bw1, sw1, sc1, bw2, sw2, sc2);
    return acc;
}

// Build: block = 256 threads = 32 nodes x 8 units; covers 29 intervals.
__global__ __launch_bounds__(256)
void build_lut_kernel(
    const float* __restrict__ bw1, const float* __restrict__ sw1,
    const float* __restrict__ sc1, const float* __restrict__ bw2,
    const float* __restrict__ sw2, const float* __restrict__ sc2)
{
    __shared__ float s_y[32];
    int tid  = threadIdx.x;
    int unit = tid & 7;
    int nl   = tid >> 3;                      // 0..31
    int m    = blockIdx.x * 29 - 1 + nl;
    float x  = fmaf((float)m, LUT_H, -8.0f);  // exact grid node

    float c = kan_unit(x, unit, bw1, sw1, sc1, bw2, sw2, sc2);
    c += __shfl_xor_sync(0xffffffffu, c, 1);
    c += __shfl_xor_sync(0xffffffffu, c, 2);
    c += __shfl_xor_sync(0xffffffffu, c, 4);
    if (unit == 0) s_y[nl] = c;
    __syncthreads();

    if (tid < 29) {
        int k = blockIdx.x * 29 + tid;
        if (k < LUT_N) {
            float y0 = s_y[tid], y1 = s_y[tid + 1];
            float y2 = s_y[tid + 2], y3 = s_y[tid + 3];
            // Lagrange cubic through (-1,y0),(0,y1),(1,y2),(2,y3) in u:
            float c0 = y1;
            float c1 = -y0 * (1.0f/3.0f) - 0.5f * y1 + y2 - y3 * (1.0f/6.0f);
            float c2 =  0.5f * y0 - y1 + 0.5f * y2;
            float c3 = (y3 - y0) * (1.0f/6.0f) + 0.5f * (y1 - y2);
            g_coef[k] = make_float4(c0, c1, c2, c3);
        }
    }
    // Publish LUT, then allow the dependent grid to proceed.
    __threadfence();
    cudaTriggerProgrammaticLaunchCompletion();
}

__global__ __launch_bounds__(256)
void kan_lut_kernel(const float4* __restrict__ xv, float4* __restrict__ outv,
                    const float* __restrict__ bw1, const float* __restrict__ sw1,
                    const float* __restrict__ sc1, const float* __restrict__ bw2,
                    const float* __restrict__ sw2, const float* __restrict__ sc2,
                    int n4)
{
    __shared__ __align__(16) float4 s_lut[LUT_N];

    int tid = threadIdx.x;
    int idx = blockIdx.x * 256 + tid;

    // 1) Independent prelude: issue the x load NOW (overlaps with the build
    //    kernel still running — x is untouched by the primary grid).
    bool valid = idx < n4;
    float4 xin = valid ? xv[idx] : make_float4(0.f, 0.f, 0.f, 0.f);

    // 2) Wait for the primary (build) grid's writes to be visible.
    cudaGridDependencySynchronize();

    // 3) Stage LUT: 512 float4 / 256 threads = 2 per thread, coalesced.
    s_lut[tid]       = __ldcg(&g_coef[tid]);
    s_lut[tid + 256] = __ldcg(&g_coef[tid + 256]);
    __syncthreads();

    // 4) Evaluate: one random LDS.128 + Horner per element.
    float xs[4] = {xin.x, xin.y, xin.z, xin.w};
    float r[4];
    bool oor_any = false;
    unsigned oor_mask = 0;

    #pragma unroll
    for (int e = 0; e < 4; e++) {
        float x = xs[e];
        float s = fmaf(x, LUT_INVH, LUT_OFS);
        float kf = floorf(s);
        int k = (int)kf;
        bool oo = (k < 0) | (k >= LUT_N);
        oor_any |= oo;
        if (oo) oor_mask |= 1u << e;
        k = max(0, min(LUT_N - 1, k));
        float u = fmaf(x, LUT_INVH, LUT_OFS - (float)k);
        float4 cf = s_lut[k];
        r[e] = fmaf(fmaf(fmaf(cf.w, u, cf.z), u, cf.y), u, cf.x);
    }

    if (oor_any) {  // essentially never taken for N(0,1) inputs
        #pragma unroll
        for (int e = 0; e < 4; e++)
            if (oor_mask & (1u << e))
                r[e] = kan_exact(xs[e], bw1, sw1, sc1, bw2, sw2, sc2);
    }

    if (valid) outv[idx] = make_float4(r[0], r[1], r[2], r[3]);
}

extern "C" void kernel_launch(void* const* d_in, const int* in_sizes, int n_in,
                              void* d_out, int out_size) {
    const float* x   = (const float*)d_in[0];
    const float* bw1 = (const float*)d_in[1];
    const float* sw1 = (const float*)d_in[2];
    const float* sc1 = (const float*)d_in[3];
    const float* bw2 = (const float*)d_in[4];
    const float* sw2 = (const float*)d_in[5];
    const float* sc2 = (const float*)d_in[6];

    int n  = in_sizes[0];   // 524288
    int n4 = n / 4;         // 131072

    build_lut_kernel<<<(LUT_N + 28) / 29, 256>>>(bw1, sw1, sc1, bw2, sw2, sc2);

    // Dependent launch with programmatic stream serialization: the grid may
    // launch while the build kernel drains; correctness is ensured by
    // cudaGridDependencySynchronize() inside the kernel.
    cudaLaunchConfig_t cfg = {};
    cfg.gridDim  = dim3((unsigned)((n4 + 255) / 256), 1, 1);   // 512
    cfg.blockDim = dim3(256, 1, 1);
    cfg.dynamicSmemBytes = 0;
    cfg.stream = 0;
    cudaLaunchAttribute attrs[1];
    attrs[0].id = cudaLaunchAttributeProgrammaticStreamSerialization;
    attrs[0].val.programmaticStreamSerializationAllowed = 1;
    cfg.attrs = attrs;
    cfg.numAttrs = 1;

    cudaLaunchKernelEx(&cfg, kan_lut_kernel,
                       (const float4*)x, (float4*)d_out,
                       bw1, sw1, sc1, bw2, sw2, sc2, n4);
}